// round 1
// baseline (speedup 1.0000x reference)
#include <cuda_runtime.h>
#include <math_constants.h>

#define NN 8192
#define HH 64
#define L2E 1.4426950408889634f
#define NEGL2E (-1.0e9f * 1.4426950408889634f)

// Scratch (device globals: allocation-free per harness rules)
__device__ float g_h[NN*HH];
__device__ float g_q[NN*HH];   // pre-scaled by gate * 0.125 * log2(e)
__device__ float g_k[NN*HH];
__device__ float g_m[NN*HH];
__device__ float g_emb[NN*HH];
__device__ float g_s[NN];      // is_stateful = node_features[:,2]
__device__ float g_gate;
__device__ float g_sbc;        // stateful_bias * (1 - t0) * log2(e)

__device__ __forceinline__ float ex2f(float x) {
    float y; asm("ex2.approx.ftz.f32 %0, %1;" : "=f"(y) : "f"(x)); return y;
}

// ---------------- Kernel 0: scalars (gate factor, stateful-bias coefficient) ----
__global__ void k_scalars(const float* __restrict__ trig, const float* __restrict__ wg,
                          const float* __restrict__ bg, const float* __restrict__ sbias) {
    int d = threadIdx.x;
    float t0 = trig[0], t1 = trig[1];
    float v = t0 * wg[d] + t1 * wg[64 + d] + bg[d];
    float sig = 1.0f / (1.0f + __expf(-v));
    #pragma unroll
    for (int o = 16; o > 0; o >>= 1) sig += __shfl_xor_sync(0xffffffffu, sig, o);
    __shared__ float ws[2];
    if ((d & 31) == 0) ws[d >> 5] = sig;
    __syncthreads();
    if (d == 0) {
        g_gate = (ws[0] + ws[1]) * (1.0f / 64.0f);
        g_sbc  = sbias[0] * (1.0f - t0) * L2E;
    }
}

// ---------------- Kernel 1: per-node MLP -> h, q(scaled), k, m ------------------
// 256 threads = 4 node-lanes x 64 dims; 8 nodes per lane-group; grid 256.
__global__ void __launch_bounds__(256) k_mlp(
    const float* __restrict__ nf, const float* __restrict__ trig,
    const float* __restrict__ w1, const float* __restrict__ b1,
    const float* __restrict__ w2, const float* __restrict__ b2,
    const float* __restrict__ wq, const float* __restrict__ bq,
    const float* __restrict__ wk, const float* __restrict__ bk,
    const float* __restrict__ wm, const float* __restrict__ bm) {
    __shared__ float h1[4][64];
    __shared__ float hh[4][64];
    int g = threadIdx.x >> 6, d = threadIdx.x & 63;
    float t0 = trig[0], t1 = trig[1];
    float qsc = g_gate * 0.125f * L2E;
    for (int it = 0; it < 8; ++it) {
        int i = blockIdx.x * 32 + g * 8 + it;
        float x0 = nf[i*3+0], x1 = nf[i*3+1], x2 = nf[i*3+2];
        float a = b1[d] + x0*w1[d] + x1*w1[64+d] + x2*w1[128+d] + t0*w1[192+d] + t1*w1[256+d];
        h1[g][d] = fmaxf(a, 0.0f);
        __syncthreads();
        float s2 = b2[d];
        #pragma unroll 8
        for (int e = 0; e < 64; ++e) s2 += h1[g][e] * w2[e*64 + d];
        hh[g][d] = s2;
        g_h[i*64 + d] = s2;
        __syncthreads();
        float q = bq[d], k = bk[d], m = bm[d];
        #pragma unroll 8
        for (int e = 0; e < 64; ++e) {
            float he = hh[g][e];
            q += he * wq[e*64 + d];
            k += he * wk[e*64 + d];
            m += he * wm[e*64 + d];
        }
        g_q[i*64 + d] = q * qsc;
        g_k[i*64 + d] = k;
        g_m[i*64 + d] = m;
        if (d == 0) g_s[i] = x2;
        __syncthreads();
    }
}

// ---------------- Kernel 2: flash attention + layernorm -------------------------
// Grid 128 blocks, 256 threads. Br=Bc=64. Thread (tr,tc) owns 4x4 micro-tile.
// smem: QsT[64][66] KsT[64][66] Ms[64][64] PT[64][66]  (67072 B dynamic)
__global__ void __launch_bounds__(256) k_attn(const float* __restrict__ adj,
                                              const float* __restrict__ lng,
                                              const float* __restrict__ lnb) {
    extern __shared__ float sm[];
    float* QsT = sm;                          // transposed: [kk][row], stride 66
    float* KsT = sm + 64*66;                  // transposed: [kk][col], stride 66
    float* Ms  = sm + 2*64*66;                // [j][d], stride 64
    float* PT  = sm + 2*64*66 + 64*64;        // [j][row], stride 66
    const int t  = threadIdx.x;
    const int tr = t >> 4, tc = t & 15;
    const int rr = tr * 4, cc = tc * 4;
    const int r0 = blockIdx.x * 64;

    // Load Q tile (transposed into smem)
    for (int idx = t; idx < 4096; idx += 256) {
        int r = idx >> 6, d = idx & 63;
        QsT[d*66 + r] = g_q[(r0 + r)*64 + d];
    }
    float sr[4], m_i[4], l_i[4], acc[4][4];
    #pragma unroll
    for (int i = 0; i < 4; ++i) {
        sr[i] = g_s[r0 + rr + i];
        m_i[i] = -CUDART_INF_F;
        l_i[i] = 0.0f;
        #pragma unroll
        for (int j = 0; j < 4; ++j) acc[i][j] = 0.0f;
    }
    const float sbc = g_sbc;

    for (int ct = 0; ct < 128; ++ct) {
        const int c0 = ct * 64;
        __syncthreads();   // prev PV done reading PT/Ms; QsT ready on first iter
        for (int idx = t; idx < 4096; idx += 256) {
            int j = idx >> 6, d = idx & 63;
            KsT[d*66 + j] = g_k[(c0 + j)*64 + d];
            Ms[idx]       = g_m[c0*64 + idx];
        }
        float sc[4];
        #pragma unroll
        for (int j = 0; j < 4; ++j) sc[j] = g_s[c0 + cc + j];
        __syncthreads();

        // S = Q K^T  (q pre-scaled by gate/8*log2e)
        float s[4][4];
        #pragma unroll
        for (int i = 0; i < 4; ++i)
            #pragma unroll
            for (int j = 0; j < 4; ++j) s[i][j] = 0.0f;
        #pragma unroll 8
        for (int kk = 0; kk < 64; ++kk) {
            float2 a0 = *(const float2*)(QsT + kk*66 + rr);
            float2 a1 = *(const float2*)(QsT + kk*66 + rr + 2);
            float2 b0 = *(const float2*)(KsT + kk*66 + cc);
            float2 b1 = *(const float2*)(KsT + kk*66 + cc + 2);
            float av[4] = {a0.x, a0.y, a1.x, a1.y};
            float bv[4] = {b0.x, b0.y, b1.x, b1.y};
            #pragma unroll
            for (int i = 0; i < 4; ++i)
                #pragma unroll
                for (int j = 0; j < 4; ++j) s[i][j] += av[i] * bv[j];
        }
        // + topo + stateful bias (all already in log2e units), tile row-max
        float tmax[4];
        #pragma unroll
        for (int i = 0; i < 4; ++i) {
            float4 a4 = *(const float4*)(adj + (size_t)(r0 + rr + i) * NN + c0 + cc);
            float aj[4] = {a4.x, a4.y, a4.z, a4.w};
            float mx = -CUDART_INF_F;
            #pragma unroll
            for (int j = 0; j < 4; ++j) {
                float av = aj[j];
                float topo = (av == 0.0f) ? NEGL2E : av * L2E;
                float v = s[i][j] + topo + sr[i] * sc[j] * sbc;
                s[i][j] = v;
                mx = fmaxf(mx, v);
            }
            tmax[i] = mx;
        }
        #pragma unroll
        for (int o = 8; o > 0; o >>= 1)
            #pragma unroll
            for (int i = 0; i < 4; ++i)
                tmax[i] = fmaxf(tmax[i], __shfl_xor_sync(0xffffffffu, tmax[i], o));
        // online softmax update (identical across the 16 threads of each row)
        float fac[4], ps[4];
        #pragma unroll
        for (int i = 0; i < 4; ++i) {
            float nm = fmaxf(m_i[i], tmax[i]);
            fac[i] = ex2f(m_i[i] - nm);
            m_i[i] = nm;
            float sum = 0.0f;
            #pragma unroll
            for (int j = 0; j < 4; ++j) {
                float p = ex2f(s[i][j] - nm);
                s[i][j] = p;
                sum += p;
            }
            ps[i] = sum;
        }
        #pragma unroll
        for (int o = 8; o > 0; o >>= 1)
            #pragma unroll
            for (int i = 0; i < 4; ++i)
                ps[i] += __shfl_xor_sync(0xffffffffu, ps[i], o);
        #pragma unroll
        for (int i = 0; i < 4; ++i) {
            l_i[i] = l_i[i] * fac[i] + ps[i];
            #pragma unroll
            for (int j = 0; j < 4; ++j) acc[i][j] *= fac[i];
        }
        // write P transposed
        #pragma unroll
        for (int j = 0; j < 4; ++j)
            #pragma unroll
            for (int i = 0; i < 4; ++i)
                PT[(cc + j)*66 + rr + i] = s[i][j];
        __syncthreads();
        // O += P @ M
        #pragma unroll 8
        for (int jp = 0; jp < 64; ++jp) {
            float2 a0 = *(const float2*)(PT + jp*66 + rr);
            float2 a1 = *(const float2*)(PT + jp*66 + rr + 2);
            float2 b0 = *(const float2*)(Ms + jp*64 + cc);
            float2 b1 = *(const float2*)(Ms + jp*64 + cc + 2);
            float av[4] = {a0.x, a0.y, a1.x, a1.y};
            float bv[4] = {b0.x, b0.y, b1.x, b1.y};
            #pragma unroll
            for (int i = 0; i < 4; ++i)
                #pragma unroll
                for (int j = 0; j < 4; ++j) acc[i][j] += av[i] * bv[j];
        }
    }

    // Epilogue: z = h + attn@m, layernorm, store emb
    float gv[4], bv2[4];
    #pragma unroll
    for (int j = 0; j < 4; ++j) { gv[j] = lng[cc + j]; bv2[j] = lnb[cc + j]; }
    #pragma unroll
    for (int i = 0; i < 4; ++i) {
        int r = r0 + rr + i;
        float inv = 1.0f / l_i[i];
        float z[4], sum = 0.0f;
        #pragma unroll
        for (int j = 0; j < 4; ++j) {
            z[j] = g_h[r*64 + cc + j] + acc[i][j] * inv;
            sum += z[j];
        }
        #pragma unroll
        for (int o = 8; o > 0; o >>= 1) sum += __shfl_xor_sync(0xffffffffu, sum, o);
        float mu = sum * (1.0f / 64.0f);
        float vs = 0.0f;
        #pragma unroll
        for (int j = 0; j < 4; ++j) { float dz = z[j] - mu; vs += dz * dz; }
        #pragma unroll
        for (int o = 8; o > 0; o >>= 1) vs += __shfl_xor_sync(0xffffffffu, vs, o);
        float rstd = rsqrtf(vs * (1.0f / 64.0f) + 1e-5f);
        float4 o4;
        o4.x = (z[0] - mu) * rstd * gv[0] + bv2[0];
        o4.y = (z[1] - mu) * rstd * gv[1] + bv2[1];
        o4.z = (z[2] - mu) * rstd * gv[2] + bv2[2];
        o4.w = (z[3] - mu) * rstd * gv[3] + bv2[3];
        *(float4*)(g_emb + r*64 + cc) = o4;
    }
}

// ---------------- Kernel 3: DQN head --------------------------------------------
__global__ void __launch_bounds__(64) k_head(
    const float* __restrict__ sa, const float* __restrict__ wa1,
    const float* __restrict__ ba1, const float* __restrict__ wa2,
    const float* __restrict__ ba2, float* __restrict__ out) {
    __shared__ float ai[68];
    __shared__ float a1s[64];
    int d = threadIdx.x;
    for (int it = 0; it < 16; ++it) {
        int i = blockIdx.x * 16 + it;
        ai[d] = g_emb[i*64 + d];
        if (d < 2) ai[64 + d] = sa[i*2 + d];
        __syncthreads();
        float a = ba1[d];
        #pragma unroll 11
        for (int e = 0; e < 66; ++e) a += ai[e] * wa1[e*64 + d];
        a1s[d] = fmaxf(a, 0.0f);
        __syncthreads();
        if (d < 3) {
            float o = ba2[d];
            #pragma unroll 8
            for (int e = 0; e < 64; ++e) o += a1s[e] * wa2[e*3 + d];
            out[i*3 + d] = o;
        }
        __syncthreads();
    }
}

extern "C" void kernel_launch(void* const* d_in, const int* in_sizes, int n_in,
                              void* d_out, int out_size) {
    const float* nf    = (const float*)d_in[0];
    const float* adj   = (const float*)d_in[1];
    const float* trig  = (const float*)d_in[2];
    const float* sa    = (const float*)d_in[3];
    const float* w1    = (const float*)d_in[4];
    const float* b1    = (const float*)d_in[5];
    const float* w2    = (const float*)d_in[6];
    const float* b2    = (const float*)d_in[7];
    const float* wq    = (const float*)d_in[8];
    const float* bq    = (const float*)d_in[9];
    const float* wk    = (const float*)d_in[10];
    const float* bk    = (const float*)d_in[11];
    const float* wg    = (const float*)d_in[12];
    const float* bg    = (const float*)d_in[13];
    const float* sbias = (const float*)d_in[14];
    const float* wm    = (const float*)d_in[15];
    const float* bm    = (const float*)d_in[16];
    const float* lng   = (const float*)d_in[17];
    const float* lnb   = (const float*)d_in[18];
    const float* wa1   = (const float*)d_in[19];
    const float* ba1   = (const float*)d_in[20];
    const float* wa2   = (const float*)d_in[21];
    const float* ba2   = (const float*)d_in[22];
    float* out = (float*)d_out;

    const int smem = (2*64*66 + 64*64 + 64*66) * 4;  // 67072 B
    cudaFuncSetAttribute(k_attn, cudaFuncAttributeMaxDynamicSharedMemorySize, smem);

    k_scalars<<<1, 64>>>(trig, wg, bg, sbias);
    k_mlp<<<256, 256>>>(nf, trig, w1, b1, w2, b2, wq, bq, wk, bk, wm, bm);
    k_attn<<<128, 256, smem>>>(adj, lng, lnb);
    k_head<<<512, 64>>>(sa, wa1, ba1, wa2, ba2, out);
}

// round 3
// speedup vs baseline: 1.5477x; 1.5477x over previous
#include <cuda_runtime.h>
#include <math_constants.h>
#include <cstdint>

#define NN 8192
#define L2E 1.4426950408889634f
#define NEGL2E (-1.0e9f * 1.4426950408889634f)

__device__ float g_h[NN*64];
__device__ float g_q[NN*64];   // pre-scaled by gate * 0.125 * log2(e)
__device__ float g_k[NN*64];
__device__ float g_m[NN*64];
__device__ float g_emb[NN*64];
__device__ float g_s[NN];
__device__ float g_gate;
__device__ float g_sbc;        // stateful_bias * (1 - t0) * log2(e)

__device__ __forceinline__ float ex2f(float x) {
    float y; asm("ex2.approx.ftz.f32 %0, %1;" : "=f"(y) : "f"(x)); return y;
}
__device__ __forceinline__ uint32_t f2tf(float x) {
    uint32_t u; asm("cvt.rna.tf32.f32 %0, %1;" : "=r"(u) : "f"(x)); return u;
}
__device__ __forceinline__ void mma_tf32(float* c, const uint32_t* a, const uint32_t* b) {
    asm volatile("mma.sync.aligned.m16n8k8.row.col.f32.tf32.tf32.f32 "
                 "{%0,%1,%2,%3},{%4,%5,%6,%7},{%8,%9},{%0,%1,%2,%3};"
                 : "+f"(c[0]), "+f"(c[1]), "+f"(c[2]), "+f"(c[3])
                 : "r"(a[0]), "r"(a[1]), "r"(a[2]), "r"(a[3]), "r"(b[0]), "r"(b[1]));
}

// ---------------- Kernel 0: scalars ---------------------------------------------
__global__ void k_scalars(const float* __restrict__ trig, const float* __restrict__ wg,
                          const float* __restrict__ bg, const float* __restrict__ sbias) {
    int d = threadIdx.x;
    float t0 = trig[0], t1 = trig[1];
    float v = t0 * wg[d] + t1 * wg[64 + d] + bg[d];
    float sig = 1.0f / (1.0f + __expf(-v));
    #pragma unroll
    for (int o = 16; o > 0; o >>= 1) sig += __shfl_xor_sync(0xffffffffu, sig, o);
    __shared__ float ws[2];
    if ((d & 31) == 0) ws[d >> 5] = sig;
    __syncthreads();
    if (d == 0) {
        g_gate = (ws[0] + ws[1]) * (1.0f / 64.0f);
        g_sbc  = sbias[0] * (1.0f - t0) * L2E;
    }
}

// ---------------- Kernel 1: per-node MLP -> h, q(scaled), k, m ------------------
__global__ void __launch_bounds__(256) k_mlp(
    const float* __restrict__ nf, const float* __restrict__ trig,
    const float* __restrict__ w1, const float* __restrict__ b1,
    const float* __restrict__ w2, const float* __restrict__ b2,
    const float* __restrict__ wq, const float* __restrict__ bq,
    const float* __restrict__ wk, const float* __restrict__ bk,
    const float* __restrict__ wm, const float* __restrict__ bm) {
    __shared__ float h1[4][64];
    __shared__ float hh[4][64];
    int g = threadIdx.x >> 6, d = threadIdx.x & 63;
    float t0 = trig[0], t1 = trig[1];
    float qsc = g_gate * 0.125f * L2E;
    for (int it = 0; it < 8; ++it) {
        int i = blockIdx.x * 32 + g * 8 + it;
        float x0 = nf[i*3+0], x1 = nf[i*3+1], x2 = nf[i*3+2];
        float a = b1[d] + x0*w1[d] + x1*w1[64+d] + x2*w1[128+d] + t0*w1[192+d] + t1*w1[256+d];
        h1[g][d] = fmaxf(a, 0.0f);
        __syncthreads();
        float s2 = b2[d];
        #pragma unroll 8
        for (int e = 0; e < 64; ++e) s2 += h1[g][e] * w2[e*64 + d];
        hh[g][d] = s2;
        g_h[i*64 + d] = s2;
        __syncthreads();
        float q = bq[d], k = bk[d], m = bm[d];
        #pragma unroll 8
        for (int e = 0; e < 64; ++e) {
            float he = hh[g][e];
            q += he * wq[e*64 + d];
            k += he * wk[e*64 + d];
            m += he * wm[e*64 + d];
        }
        g_q[i*64 + d] = q * qsc;
        g_k[i*64 + d] = k;
        g_m[i*64 + d] = m;
        if (d == 0) g_s[i] = x2;
        __syncthreads();
    }
}

// ---------------- Kernel 2: flash attention + layernorm (tf32 mma.sync) ---------
// Grid 128 blocks, 256 threads (8 warps, 4x2 warp grid, warp tile 16x32).
// smem floats: Qs 64x68, Ks 64x68, Ms 64x72, Ps 64x68, redmax 2x64, redsum 2x64
#define SQ 0
#define SK 4352
#define SM_ 8704
#define SP 13312
#define SRMAX 17664
#define SRSUM 17792
#define SMEM_FLOATS 17920

__global__ void __launch_bounds__(256) k_attn(const float* __restrict__ adj,
                                              const float* __restrict__ lng,
                                              const float* __restrict__ lnb) {
    extern __shared__ float smem[];
    float* Qs = smem + SQ;
    float* Ks = smem + SK;
    float* Ms = smem + SM_;
    float* Ps = smem + SP;
    float* redmax = smem + SRMAX;   // [2][64]
    float* redsum = smem + SRSUM;   // [2][64]
    float* zbuf = smem + SK;        // reuse Ks after loop, stride 66

    const int t = threadIdx.x;
    const int warp = t >> 5;
    const int lane = t & 31;
    const int wr = warp >> 1, wc = warp & 1;
    const int qr = lane >> 2;        // 0..7  (mma groupID)
    const int four = lane & 3;       // 0..3  (mma threadID_in_group)
    const int r0 = blockIdx.x * 64;
    const int rowa = wr * 16 + qr;   // tile-local row of c0/c1; +8 for c2/c3

    // Load Q tile once (tf32-converted)
    for (int idx = t; idx < 1024; idx += 256) {
        int r = idx >> 4, c4 = (idx & 15) * 4;
        float4 v = *(const float4*)(g_q + (size_t)(r0 + r) * 64 + c4);
        uint32_t* dst = (uint32_t*)(Qs + r * 68 + c4);
        dst[0] = f2tf(v.x); dst[1] = f2tf(v.y); dst[2] = f2tf(v.z); dst[3] = f2tf(v.w);
    }

    float sr[2];
    sr[0] = g_s[r0 + rowa];
    sr[1] = g_s[r0 + rowa + 8];
    float m_i[2] = {-CUDART_INF_F, -CUDART_INF_F};
    float l_i[2] = {0.0f, 0.0f};
    float acc_o[4][4];
    #pragma unroll
    for (int ni = 0; ni < 4; ++ni)
        #pragma unroll
        for (int e = 0; e < 4; ++e) acc_o[ni][e] = 0.0f;
    const float sbc = g_sbc;

    for (int ct = 0; ct < 128; ++ct) {
        const int c0 = ct * 64;
        __syncthreads();
        // Load K, M tiles (tf32-converted)
        for (int idx = t; idx < 1024; idx += 256) {
            int r = idx >> 4, c4 = (idx & 15) * 4;
            float4 kv = *(const float4*)(g_k + (size_t)(c0 + r) * 64 + c4);
            uint32_t* kd = (uint32_t*)(Ks + r * 68 + c4);
            kd[0] = f2tf(kv.x); kd[1] = f2tf(kv.y); kd[2] = f2tf(kv.z); kd[3] = f2tf(kv.w);
            float4 mv = *(const float4*)(g_m + (size_t)(c0 + r) * 64 + c4);
            uint32_t* md = (uint32_t*)(Ms + r * 72 + c4);
            md[0] = f2tf(mv.x); md[1] = f2tf(mv.y); md[2] = f2tf(mv.z); md[3] = f2tf(mv.w);
        }
        __syncthreads();

        // S = Q K^T (tensor cores)
        float s[4][4];
        #pragma unroll
        for (int ni = 0; ni < 4; ++ni)
            #pragma unroll
            for (int e = 0; e < 4; ++e) s[ni][e] = 0.0f;
        #pragma unroll
        for (int kk = 0; kk < 8; ++kk) {
            uint32_t a[4], b[2];
            const uint32_t* qp = (const uint32_t*)Qs + rowa * 68 + kk * 8 + four;
            a[0] = qp[0]; a[1] = qp[8 * 68]; a[2] = qp[4]; a[3] = qp[8 * 68 + 4];
            #pragma unroll
            for (int ni = 0; ni < 4; ++ni) {
                const uint32_t* kp = (const uint32_t*)Ks + (wc * 32 + ni * 8 + qr) * 68 + kk * 8 + four;
                b[0] = kp[0]; b[1] = kp[4];
                mma_tf32(s[ni], a, b);
            }
        }

        // + topo + stateful bias, thread-local row max
        float lmax[2] = {-CUDART_INF_F, -CUDART_INF_F};
        #pragma unroll
        for (int ni = 0; ni < 4; ++ni) {
            int cgl = c0 + wc * 32 + ni * 8 + 2 * four;
            float2 sc2 = *(const float2*)(g_s + cgl);
            #pragma unroll
            for (int h = 0; h < 2; ++h) {
                int rgl = r0 + rowa + h * 8;
                float2 a2 = *(const float2*)(adj + (size_t)rgl * NN + cgl);
                float v0 = s[ni][h*2+0] + ((a2.x == 0.0f) ? NEGL2E : a2.x * L2E) + sr[h] * sc2.x * sbc;
                float v1 = s[ni][h*2+1] + ((a2.y == 0.0f) ? NEGL2E : a2.y * L2E) + sr[h] * sc2.y * sbc;
                s[ni][h*2+0] = v0; s[ni][h*2+1] = v1;
                lmax[h] = fmaxf(lmax[h], fmaxf(v0, v1));
            }
        }
        #pragma unroll
        for (int o = 1; o <= 2; o <<= 1) {
            lmax[0] = fmaxf(lmax[0], __shfl_xor_sync(0xffffffffu, lmax[0], o));
            lmax[1] = fmaxf(lmax[1], __shfl_xor_sync(0xffffffffu, lmax[1], o));
        }
        if (four == 0) {
            redmax[wc * 64 + rowa] = lmax[0];
            redmax[wc * 64 + rowa + 8] = lmax[1];
        }
        __syncthreads();
        float fac[2], psum[2] = {0.0f, 0.0f};
        #pragma unroll
        for (int h = 0; h < 2; ++h) {
            float tm = fmaxf(redmax[rowa + h * 8], redmax[64 + rowa + h * 8]);
            float nm = fmaxf(m_i[h], tm);
            fac[h] = ex2f(m_i[h] - nm);
            m_i[h] = nm;
        }
        // p = exp2, partial sums, store P (tf32)
        #pragma unroll
        for (int ni = 0; ni < 4; ++ni) {
            int col = wc * 32 + ni * 8 + 2 * four;
            #pragma unroll
            for (int h = 0; h < 2; ++h) {
                float p0 = ex2f(s[ni][h*2+0] - m_i[h]);
                float p1 = ex2f(s[ni][h*2+1] - m_i[h]);
                psum[h] += p0 + p1;
                uint2 pp; pp.x = f2tf(p0); pp.y = f2tf(p1);
                *(uint2*)((uint32_t*)Ps + (rowa + h * 8) * 68 + col) = pp;
            }
        }
        #pragma unroll
        for (int o = 1; o <= 2; o <<= 1) {
            psum[0] += __shfl_xor_sync(0xffffffffu, psum[0], o);
            psum[1] += __shfl_xor_sync(0xffffffffu, psum[1], o);
        }
        if (four == 0) {
            redsum[wc * 64 + rowa] = psum[0];
            redsum[wc * 64 + rowa + 8] = psum[1];
        }
        // rescale accumulator while the reduction lands
        #pragma unroll
        for (int ni = 0; ni < 4; ++ni) {
            acc_o[ni][0] *= fac[0]; acc_o[ni][1] *= fac[0];
            acc_o[ni][2] *= fac[1]; acc_o[ni][3] *= fac[1];
        }
        __syncthreads();
        #pragma unroll
        for (int h = 0; h < 2; ++h)
            l_i[h] = l_i[h] * fac[h] + redsum[rowa + h * 8] + redsum[64 + rowa + h * 8];

        // O += P @ M (tensor cores)
        #pragma unroll
        for (int kk = 0; kk < 8; ++kk) {
            uint32_t a[4], b[2];
            const uint32_t* pp = (const uint32_t*)Ps + rowa * 68 + kk * 8 + four;
            a[0] = pp[0]; a[1] = pp[8 * 68]; a[2] = pp[4]; a[3] = pp[8 * 68 + 4];
            #pragma unroll
            for (int ni = 0; ni < 4; ++ni) {
                const uint32_t* mp = (const uint32_t*)Ms + (kk * 8 + four) * 72 + wc * 32 + ni * 8 + qr;
                b[0] = mp[0]; b[1] = mp[4 * 72];
                mma_tf32(acc_o[ni], a, b);
            }
        }
    }

    // Epilogue: z = h + O/l -> smem, then per-row layernorm
    __syncthreads();
    float invl[2] = {1.0f / l_i[0], 1.0f / l_i[1]};
    #pragma unroll
    for (int ni = 0; ni < 4; ++ni) {
        int col = wc * 32 + ni * 8 + 2 * four;
        #pragma unroll
        for (int h = 0; h < 2; ++h) {
            int row = rowa + h * 8;
            float2 h2 = *(const float2*)(g_h + (size_t)(r0 + row) * 64 + col);
            float2 z2;
            z2.x = h2.x + acc_o[ni][h*2+0] * invl[h];
            z2.y = h2.y + acc_o[ni][h*2+1] * invl[h];
            *(float2*)(zbuf + row * 66 + col) = z2;
        }
    }
    __syncthreads();
    if (t < 64) {
        float sum = 0.0f;
        #pragma unroll 16
        for (int c = 0; c < 64; ++c) sum += zbuf[t * 66 + c];
        float mu = sum * (1.0f / 64.0f);
        float sq = 0.0f;
        #pragma unroll 16
        for (int c = 0; c < 64; ++c) { float d = zbuf[t * 66 + c] - mu; sq += d * d; }
        float rstd = rsqrtf(sq * (1.0f / 64.0f) + 1e-5f);
        #pragma unroll 16
        for (int c = 0; c < 64; ++c)
            g_emb[(size_t)(r0 + t) * 64 + c] = (zbuf[t * 66 + c] - mu) * rstd * lng[c] + lnb[c];
    }
}

// ---------------- Kernel 3: DQN head (256-thread blocks) ------------------------
__global__ void __launch_bounds__(256) k_head(
    const float* __restrict__ sa, const float* __restrict__ wa1,
    const float* __restrict__ ba1, const float* __restrict__ wa2,
    const float* __restrict__ ba2, float* __restrict__ out) {
    __shared__ float ai[4][68];
    __shared__ float a1s[4][64];
    int g = threadIdx.x >> 6, d = threadIdx.x & 63;
    for (int it = 0; it < 16; ++it) {
        int i = (blockIdx.x * 4 + g) * 16 + it;
        ai[g][d] = g_emb[i*64 + d];
        if (d < 2) ai[g][64 + d] = sa[i*2 + d];
        __syncthreads();
        float a = ba1[d];
        #pragma unroll 11
        for (int e = 0; e < 66; ++e) a += ai[g][e] * wa1[e*64 + d];
        a1s[g][d] = fmaxf(a, 0.0f);
        __syncthreads();
        if (d < 3) {
            float o = ba2[d];
            #pragma unroll 8
            for (int e = 0; e < 64; ++e) o += a1s[g][e] * wa2[e*3 + d];
            out[i*3 + d] = o;
        }
        __syncthreads();
    }
}

extern "C" void kernel_launch(void* const* d_in, const int* in_sizes, int n_in,
                              void* d_out, int out_size) {
    const float* nf    = (const float*)d_in[0];
    const float* adj   = (const float*)d_in[1];
    const float* trig  = (const float*)d_in[2];
    const float* sa    = (const float*)d_in[3];
    const float* w1    = (const float*)d_in[4];
    const float* b1    = (const float*)d_in[5];
    const float* w2    = (const float*)d_in[6];
    const float* b2    = (const float*)d_in[7];
    const float* wq    = (const float*)d_in[8];
    const float* bq    = (const float*)d_in[9];
    const float* wk    = (const float*)d_in[10];
    const float* bk    = (const float*)d_in[11];
    const float* wg    = (const float*)d_in[12];
    const float* bg    = (const float*)d_in[13];
    const float* sbias = (const float*)d_in[14];
    const float* wm    = (const float*)d_in[15];
    const float* bm    = (const float*)d_in[16];
    const float* lng   = (const float*)d_in[17];
    const float* lnb   = (const float*)d_in[18];
    const float* wa1   = (const float*)d_in[19];
    const float* ba1   = (const float*)d_in[20];
    const float* wa2   = (const float*)d_in[21];
    const float* ba2   = (const float*)d_in[22];
    float* out = (float*)d_out;

    const int smem = SMEM_FLOATS * 4;  // 71680 B
    cudaFuncSetAttribute(k_attn, cudaFuncAttributeMaxDynamicSharedMemorySize, smem);

    k_scalars<<<1, 64>>>(trig, wg, bg, sbias);
    k_mlp<<<256, 256>>>(nf, trig, w1, b1, w2, b2, wq, bq, wk, bk, wm, bm);
    k_attn<<<128, 256, smem>>>(adj, lng, lnb);
    k_head<<<128, 256>>>(sa, wa1, ba1, wa2, ba2, out);
}

// round 7
// speedup vs baseline: 4.2519x; 2.7473x over previous
#include <cuda_runtime.h>
#include <cuda_bf16.h>
#include <math_constants.h>
#include <cstdint>

#define NN 8192
#define L2E 1.4426950408889634f

__device__ float g_h[NN*64];
__device__ __nv_bfloat16 g_q[NN*64];   // pre-scaled by gate * 0.125 * log2(e)
__device__ __nv_bfloat16 g_k[NN*64];
__device__ __nv_bfloat16 g_mT[64*NN];  // transposed: [dim][node]
__device__ float g_emb[NN*64];
__device__ float g_s[NN];
__device__ float g_gate;
__device__ float g_sbc;                // stateful_bias * (1 - t0) * log2(e)

__device__ __forceinline__ float ex2f(float x) {
    float y; asm("ex2.approx.ftz.f32 %0, %1;" : "=f"(y) : "f"(x)); return y;
}
__device__ __forceinline__ uint32_t pkbf(float a, float b) {
    __nv_bfloat162 t = __floats2bfloat162_rn(a, b);
    return *reinterpret_cast<uint32_t*>(&t);
}
__device__ __forceinline__ void mma_bf16(float* c, const uint32_t* a, const uint32_t* b) {
    asm volatile("mma.sync.aligned.m16n8k16.row.col.f32.bf16.bf16.f32 "
                 "{%0,%1,%2,%3},{%4,%5,%6,%7},{%8,%9},{%0,%1,%2,%3};"
                 : "+f"(c[0]), "+f"(c[1]), "+f"(c[2]), "+f"(c[3])
                 : "r"(a[0]), "r"(a[1]), "r"(a[2]), "r"(a[3]), "r"(b[0]), "r"(b[1]));
}
#define CP16(d, s) asm volatile("cp.async.cg.shared.global [%0], [%1], 16;" :: "r"(d), "l"(s))
#define CPCOM()    asm volatile("cp.async.commit_group;" ::: "memory")
#define CPWAIT(n)  asm volatile("cp.async.wait_group %0;" :: "n"(n) : "memory")

// ---------------- Kernel 0: scalars ---------------------------------------------
__global__ void k_scalars(const float* __restrict__ trig, const float* __restrict__ wg,
                          const float* __restrict__ bg, const float* __restrict__ sbias) {
    int d = threadIdx.x;
    float t0 = trig[0], t1 = trig[1];
    float v = t0 * wg[d] + t1 * wg[64 + d] + bg[d];
    float sig = 1.0f / (1.0f + __expf(-v));
    #pragma unroll
    for (int o = 16; o > 0; o >>= 1) sig += __shfl_xor_sync(0xffffffffu, sig, o);
    __shared__ float ws[2];
    if ((d & 31) == 0) ws[d >> 5] = sig;
    __syncthreads();
    if (d == 0) {
        g_gate = (ws[0] + ws[1]) * (1.0f / 64.0f);
        g_sbc  = sbias[0] * (1.0f - t0) * L2E;
    }
}

// ---------------- Kernel 1: per-node MLP -> h(f32), q/k bf16, mT bf16 -----------
__global__ void __launch_bounds__(256) k_mlp(
    const float* __restrict__ nf, const float* __restrict__ trig,
    const float* __restrict__ w1, const float* __restrict__ b1,
    const float* __restrict__ w2, const float* __restrict__ b2,
    const float* __restrict__ wq, const float* __restrict__ bq,
    const float* __restrict__ wk, const float* __restrict__ bk,
    const float* __restrict__ wm, const float* __restrict__ bm) {
    __shared__ float h1[4][64];
    __shared__ float hh[4][64];
    __shared__ float stg[64][36];   // m staging for transpose: [dim][local node]
    int g = threadIdx.x >> 6, d = threadIdx.x & 63;
    float t0 = trig[0], t1 = trig[1];
    float qsc = g_gate * 0.125f * L2E;
    int i0 = blockIdx.x * 32;
    for (int it = 0; it < 8; ++it) {
        int ln = g * 8 + it;
        int i = i0 + ln;
        float x0 = nf[i*3+0], x1 = nf[i*3+1], x2 = nf[i*3+2];
        float a = b1[d] + x0*w1[d] + x1*w1[64+d] + x2*w1[128+d] + t0*w1[192+d] + t1*w1[256+d];
        h1[g][d] = fmaxf(a, 0.0f);
        __syncthreads();
        float s2 = b2[d];
        #pragma unroll 8
        for (int e = 0; e < 64; ++e) s2 += h1[g][e] * w2[e*64 + d];
        hh[g][d] = s2;
        g_h[i*64 + d] = s2;
        __syncthreads();
        float q = bq[d], k = bk[d], m = bm[d];
        #pragma unroll 8
        for (int e = 0; e < 64; ++e) {
            float he = hh[g][e];
            q += he * wq[e*64 + d];
            k += he * wk[e*64 + d];
            m += he * wm[e*64 + d];
        }
        g_q[i*64 + d] = __float2bfloat16(q * qsc);
        g_k[i*64 + d] = __float2bfloat16(k);
        stg[d][ln] = m;
        if (d == 0) g_s[i] = x2;
        __syncthreads();
    }
    // transposed write-out of m
    int dd = threadIdx.x >> 2, p = threadIdx.x & 3;
    float4 v0 = *(float4*)&stg[dd][p*8];
    float4 v1 = *(float4*)&stg[dd][p*8 + 4];
    uint32_t o[4] = {pkbf(v0.x, v0.y), pkbf(v0.z, v0.w), pkbf(v1.x, v1.y), pkbf(v1.z, v1.w)};
    *(uint4*)(g_mT + (size_t)dd*NN + i0 + p*8) = *(uint4*)o;
}

// ---------------- Kernel 2: flash attention (no-max softmax) + layernorm --------
// 8 warps = 4x2 grid; warp tile 16x32; bf16 mma m16n8k16; cp.async triple buffer.
#define KSTR 36
#define TILE_W (64*KSTR)         // 2304 words per tile
#define OFF_K 0                  // 3 tiles
#define OFF_M (3*TILE_W)         // 6912, 3 tiles
#define OFF_Q (6*TILE_W)         // 13824
#define OFF_P (7*TILE_W)         // 16128
#define OFF_RED (8*TILE_W)       // 18432, 128 words
#define SMEM_WORDS (8*TILE_W + 128)

__global__ void __launch_bounds__(256) k_attn(const float* __restrict__ adj,
                                              const float* __restrict__ lng,
                                              const float* __restrict__ lnb) {
    extern __shared__ uint32_t smw[];
    const int t = threadIdx.x;
    const int warp = t >> 5, lane = t & 31;
    const int wr = warp >> 1, wc = warp & 1;
    const int qr = lane >> 2, four = lane & 3;
    const int r0 = blockIdx.x * 64;
    const int rowa = wr * 16 + qr;
    const uint32_t sbase = (uint32_t)__cvta_generic_to_shared(smw);

    // tile copy helper (K + Mt) via cp.async
    auto cpKM = [&](int tile, int buf) {
        uint32_t dk = sbase + (OFF_K + buf * TILE_W) * 4;
        uint32_t dm = sbase + (OFF_M + buf * TILE_W) * 4;
        #pragma unroll
        for (int rep = 0; rep < 2; ++rep) {
            int idx = t + rep * 256;
            int r = idx >> 3, c = idx & 7;
            CP16(dk + (r * KSTR + c * 4) * 4, g_k + (size_t)(tile * 64 + r) * 64 + c * 8);
            CP16(dm + (r * KSTR + c * 4) * 4, g_mT + (size_t)r * NN + tile * 64 + c * 8);
        }
    };
    // prologue: Q + tile0 (group0), tile1 (group1)
    {
        uint32_t dq = sbase + OFF_Q * 4;
        #pragma unroll
        for (int rep = 0; rep < 2; ++rep) {
            int idx = t + rep * 256;
            int r = idx >> 3, c = idx & 7;
            CP16(dq + (r * KSTR + c * 4) * 4, g_q + (size_t)(r0 + r) * 64 + c * 8);
        }
        cpKM(0, 0); CPCOM();
        cpKM(1, 1); CPCOM();
    }

    const float sbc = g_sbc;
    const float sr0 = g_s[r0 + rowa];
    const float sr1 = g_s[r0 + rowa + 8];
    const float* adjr0 = adj + (size_t)(r0 + rowa) * NN + wc * 32 + 2 * four;
    const float* adjr1 = adjr0 + (size_t)8 * NN;

    const uint32_t* Qw = smw + OFF_Q;
    uint32_t* Pw = smw + OFF_P;
    float* redl = (float*)(smw + OFF_RED);

    float psum0 = 0.0f, psum1 = 0.0f;
    float acc[4][4];
    #pragma unroll
    for (int ni = 0; ni < 4; ++ni)
        #pragma unroll
        for (int e = 0; e < 4; ++e) acc[ni][e] = 0.0f;

    for (int ct = 0; ct < 128; ++ct) {
        const int c0 = ct * 64;
        // issue adj + g_s loads for THIS iter early (consumed after QK mma)
        float2 adjv[8], scv[4];
        #pragma unroll
        for (int ni = 0; ni < 4; ++ni) {
            scv[ni]      = *(const float2*)(g_s + c0 + wc * 32 + ni * 8 + 2 * four);
            adjv[ni*2+0] = *(const float2*)(adjr0 + c0 + ni * 8);
            adjv[ni*2+1] = *(const float2*)(adjr1 + c0 + ni * 8);
        }
        CPWAIT(1);
        __syncthreads();   // tile ct visible to all; all reads of buf (ct+2)%3 are done
        int nt = ct + 2; if (nt > 127) nt = 127;
        cpKM(nt, (ct + 2) % 3); CPCOM();

        const uint32_t* Kb = smw + OFF_K + (ct % 3) * TILE_W;
        const uint32_t* Mb = smw + OFF_M + (ct % 3) * TILE_W;

        // S = Q K^T
        float S[4][4];
        #pragma unroll
        for (int ni = 0; ni < 4; ++ni)
            #pragma unroll
            for (int e = 0; e < 4; ++e) S[ni][e] = 0.0f;
        #pragma unroll
        for (int kk = 0; kk < 4; ++kk) {
            uint32_t a[4], b[2];
            const uint32_t* qp = Qw + rowa * KSTR + kk * 8 + four;
            a[0] = qp[0]; a[1] = qp[8 * KSTR]; a[2] = qp[4]; a[3] = qp[8 * KSTR + 4];
            #pragma unroll
            for (int ni = 0; ni < 4; ++ni) {
                const uint32_t* kp = Kb + (wc * 32 + ni * 8 + qr) * KSTR + kk * 8 + four;
                b[0] = kp[0]; b[1] = kp[4];
                mma_bf16(S[ni], a, b);
            }
        }

        // p = adj ? exp2(s + sb) : 0   (no max; topo=+1 is a row constant, dropped)
        #pragma unroll
        for (int ni = 0; ni < 4; ++ni) {
            float2 a0 = adjv[ni*2+0], a1 = adjv[ni*2+1], sc2 = scv[ni];
            float p00 = (a0.x == 0.0f) ? 0.0f : ex2f(S[ni][0] + sr0 * sc2.x * sbc);
            float p01 = (a0.y == 0.0f) ? 0.0f : ex2f(S[ni][1] + sr0 * sc2.y * sbc);
            float p10 = (a1.x == 0.0f) ? 0.0f : ex2f(S[ni][2] + sr1 * sc2.x * sbc);
            float p11 = (a1.y == 0.0f) ? 0.0f : ex2f(S[ni][3] + sr1 * sc2.y * sbc);
            psum0 += p00 + p01;
            psum1 += p10 + p11;
            int cw = wc * 16 + ni * 4 + four;
            Pw[rowa * KSTR + cw]       = pkbf(p00, p01);
            Pw[(rowa + 8) * KSTR + cw] = pkbf(p10, p11);
        }
        asm volatile("bar.sync %0, %1;" :: "r"(wr + 1), "r"(64) : "memory");  // pair barrier

        // O += P @ M
        #pragma unroll
        for (int kk = 0; kk < 4; ++kk) {
            uint32_t a[4], b[2];
            const uint32_t* pp = Pw + rowa * KSTR + kk * 8 + four;
            a[0] = pp[0]; a[1] = pp[8 * KSTR]; a[2] = pp[4]; a[3] = pp[8 * KSTR + 4];
            #pragma unroll
            for (int ni = 0; ni < 4; ++ni) {
                const uint32_t* mp = Mb + (wc * 32 + ni * 8 + qr) * KSTR + kk * 8 + four;
                b[0] = mp[0]; b[1] = mp[4];
                mma_bf16(acc[ni], a, b);
            }
        }
    }
    CPWAIT(0);
    __syncthreads();   // no in-flight cp.async; safe to reuse smem

    // l reduction (sum over the four-group, then across the wc pair)
    psum0 += __shfl_xor_sync(0xffffffffu, psum0, 1);
    psum0 += __shfl_xor_sync(0xffffffffu, psum0, 2);
    psum1 += __shfl_xor_sync(0xffffffffu, psum1, 1);
    psum1 += __shfl_xor_sync(0xffffffffu, psum1, 2);
    if (four == 0) {
        redl[wc * 64 + rowa]     = psum0;
        redl[wc * 64 + rowa + 8] = psum1;
    }
    __syncthreads();
    float inv0 = 1.0f / (redl[rowa]     + redl[64 + rowa]);
    float inv1 = 1.0f / (redl[rowa + 8] + redl[64 + rowa + 8]);

    // z = h + O/l -> zbuf, then per-row layernorm
    float* zbuf = (float*)smw;   // 64 rows x stride 66
    #pragma unroll
    for (int ni = 0; ni < 4; ++ni) {
        int col = wc * 32 + ni * 8 + 2 * four;
        float2 h0 = *(const float2*)(g_h + (size_t)(r0 + rowa) * 64 + col);
        float2 h1 = *(const float2*)(g_h + (size_t)(r0 + rowa + 8) * 64 + col);
        float2 z0, z1;
        z0.x = h0.x + acc[ni][0] * inv0;  z0.y = h0.y + acc[ni][1] * inv0;
        z1.x = h1.x + acc[ni][2] * inv1;  z1.y = h1.y + acc[ni][3] * inv1;
        *(float2*)(zbuf + rowa * 66 + col)       = z0;
        *(float2*)(zbuf + (rowa + 8) * 66 + col) = z1;
    }
    __syncthreads();
    if (t < 64) {
        float sum = 0.0f;
        #pragma unroll 16
        for (int c = 0; c < 64; ++c) sum += zbuf[t * 66 + c];
        float mu = sum * (1.0f / 64.0f);
        float sq = 0.0f;
        #pragma unroll 16
        for (int c = 0; c < 64; ++c) { float dz = zbuf[t * 66 + c] - mu; sq += dz * dz; }
        float rstd = rsqrtf(sq * (1.0f / 64.0f) + 1e-5f);
        #pragma unroll 16
        for (int c = 0; c < 64; ++c)
            g_emb[(size_t)(r0 + t) * 64 + c] = (zbuf[t * 66 + c] - mu) * rstd * lng[c] + lnb[c];
    }
}

// ---------------- Kernel 3: DQN head — warp per node, no in-loop block barriers --
__global__ void __launch_bounds__(256) k_head(
    const float* __restrict__ sa, const float* __restrict__ wa1,
    const float* __restrict__ ba1, const float* __restrict__ wa2,
    const float* __restrict__ ba2, float* __restrict__ out) {
    __shared__ float swa1[66*64];
    __shared__ float swa2[64*3];
    int t = threadIdx.x;
    for (int idx = t; idx < 66*64; idx += 256) swa1[idx] = wa1[idx];
    if (t < 192) swa2[t] = wa2[t];
    __syncthreads();
    int warp = t >> 5, lane = t & 31;
    float b0 = ba1[2*lane], b1 = ba1[2*lane+1];
    for (int it = 0; it < 4; ++it) {
        int i = blockIdx.x * 32 + it * 8 + warp;
        float2 e = *(const float2*)(g_emb + (size_t)i * 64 + 2 * lane);
        float2 s2 = *(const float2*)(sa + i * 2);
        float acc0 = b0, acc1 = b1;
        #pragma unroll
        for (int ee = 0; ee < 64; ++ee) {
            float v = __shfl_sync(0xffffffffu, (ee & 1) ? e.y : e.x, ee >> 1);
            float2 w = *(const float2*)(swa1 + ee * 64 + 2 * lane);
            acc0 += v * w.x; acc1 += v * w.y;
        }
        { float2 w = *(const float2*)(swa1 + 64*64 + 2*lane); acc0 += s2.x * w.x; acc1 += s2.x * w.y; }
        { float2 w = *(const float2*)(swa1 + 65*64 + 2*lane); acc0 += s2.y * w.x; acc1 += s2.y * w.y; }
        acc0 = fmaxf(acc0, 0.0f); acc1 = fmaxf(acc1, 0.0f);
        float o0 = acc0 * swa2[(2*lane)*3+0] + acc1 * swa2[(2*lane+1)*3+0];
        float o1 = acc0 * swa2[(2*lane)*3+1] + acc1 * swa2[(2*lane+1)*3+1];
        float o2 = acc0 * swa2[(2*lane)*3+2] + acc1 * swa2[(2*lane+1)*3+2];
        #pragma unroll
        for (int off = 16; off > 0; off >>= 1) {
            o0 += __shfl_xor_sync(0xffffffffu, o0, off);
            o1 += __shfl_xor_sync(0xffffffffu, o1, off);
            o2 += __shfl_xor_sync(0xffffffffu, o2, off);
        }
        if (lane == 0) {
            out[i*3+0] = o0 + ba2[0];
            out[i*3+1] = o1 + ba2[1];
            out[i*3+2] = o2 + ba2[2];
        }
    }
}

extern "C" void kernel_launch(void* const* d_in, const int* in_sizes, int n_in,
                              void* d_out, int out_size) {
    const float* nf    = (const float*)d_in[0];
    const float* adj   = (const float*)d_in[1];
    const float* trig  = (const float*)d_in[2];
    const float* sa    = (const float*)d_in[3];
    const float* w1    = (const float*)d_in[4];
    const float* b1    = (const float*)d_in[5];
    const float* w2    = (const float*)d_in[6];
    const float* b2    = (const float*)d_in[7];
    const float* wq    = (const float*)d_in[8];
    const float* bq    = (const float*)d_in[9];
    const float* wk    = (const float*)d_in[10];
    const float* bk    = (const float*)d_in[11];
    const float* wg    = (const float*)d_in[12];
    const float* bg    = (const float*)d_in[13];
    const float* sbias = (const float*)d_in[14];
    const float* wm    = (const float*)d_in[15];
    const float* bm    = (const float*)d_in[16];
    const float* lng   = (const float*)d_in[17];
    const float* lnb   = (const float*)d_in[18];
    const float* wa1   = (const float*)d_in[19];
    const float* ba1   = (const float*)d_in[20];
    const float* wa2   = (const float*)d_in[21];
    const float* ba2   = (const float*)d_in[22];
    float* out = (float*)d_out;

    const int smem = SMEM_WORDS * 4;  // 74240 B
    cudaFuncSetAttribute(k_attn, cudaFuncAttributeMaxDynamicSharedMemorySize, smem);

    k_scalars<<<1, 64>>>(trig, wg, bg, sbias);
    k_mlp<<<256, 256>>>(nf, trig, w1, b1, w2, b2, wq, bq, wk, bk, wm, bm);
    k_attn<<<128, 256, smem>>>(adj, lng, lnb);
    k_head<<<256, 256>>>(sa, wa1, ba1, wa2, ba2, out);
}

// round 8
// speedup vs baseline: 5.1010x; 1.1997x over previous
#include <cuda_runtime.h>
#include <cuda_bf16.h>
#include <math_constants.h>
#include <cstdint>

#define NN 8192
#define L2E 1.4426950408889634f

__device__ float g_h[NN*64];
__device__ __nv_bfloat16 g_q[NN*64];   // pre-scaled by gate * 0.125 * log2(e)
__device__ __nv_bfloat16 g_k[NN*64];
__device__ __nv_bfloat16 g_mT[64*NN];  // transposed: [dim][node]
__device__ float g_emb[NN*64];
__device__ float g_s[NN];
__device__ float g_gate;
__device__ float g_sbc;                // stateful_bias * (1 - t0) * log2(e)

__device__ __forceinline__ float ex2f(float x) {
    float y; asm("ex2.approx.ftz.f32 %0, %1;" : "=f"(y) : "f"(x)); return y;
}
__device__ __forceinline__ uint32_t pkbf(float a, float b) {
    __nv_bfloat162 t = __floats2bfloat162_rn(a, b);
    return *reinterpret_cast<uint32_t*>(&t);
}
__device__ __forceinline__ void mma_bf16(float* c, const uint32_t* a, const uint32_t* b) {
    asm volatile("mma.sync.aligned.m16n8k16.row.col.f32.bf16.bf16.f32 "
                 "{%0,%1,%2,%3},{%4,%5,%6,%7},{%8,%9},{%0,%1,%2,%3};"
                 : "+f"(c[0]), "+f"(c[1]), "+f"(c[2]), "+f"(c[3])
                 : "r"(a[0]), "r"(a[1]), "r"(a[2]), "r"(a[3]), "r"(b[0]), "r"(b[1]));
}
#define CP16(d, s) asm volatile("cp.async.cg.shared.global [%0], [%1], 16;" :: "r"(d), "l"(s))
#define CPCOM()    asm volatile("cp.async.commit_group;" ::: "memory")
#define CPWAIT(n)  asm volatile("cp.async.wait_group %0;" :: "n"(n) : "memory")

// ---------------- Kernel 0: scalars ---------------------------------------------
__global__ void k_scalars(const float* __restrict__ trig, const float* __restrict__ wg,
                          const float* __restrict__ bg, const float* __restrict__ sbias) {
    int d = threadIdx.x;
    float t0 = trig[0], t1 = trig[1];
    float v = t0 * wg[d] + t1 * wg[64 + d] + bg[d];
    float sig = 1.0f / (1.0f + __expf(-v));
    #pragma unroll
    for (int o = 16; o > 0; o >>= 1) sig += __shfl_xor_sync(0xffffffffu, sig, o);
    __shared__ float ws[2];
    if ((d & 31) == 0) ws[d >> 5] = sig;
    __syncthreads();
    if (d == 0) {
        g_gate = (ws[0] + ws[1]) * (1.0f / 64.0f);
        g_sbc  = sbias[0] * (1.0f - t0) * L2E;
    }
}

// ---------------- Kernel 1: per-node MLP -> h(f32), q/k bf16, mT bf16 -----------
__global__ void __launch_bounds__(256) k_mlp(
    const float* __restrict__ nf, const float* __restrict__ trig,
    const float* __restrict__ w1, const float* __restrict__ b1,
    const float* __restrict__ w2, const float* __restrict__ b2,
    const float* __restrict__ wq, const float* __restrict__ bq,
    const float* __restrict__ wk, const float* __restrict__ bk,
    const float* __restrict__ wm, const float* __restrict__ bm) {
    __shared__ float h1[4][64];
    __shared__ float hh[4][64];
    __shared__ float stg[64][36];   // m staging for transpose: [dim][local node]
    int g = threadIdx.x >> 6, d = threadIdx.x & 63;
    float t0 = trig[0], t1 = trig[1];
    float qsc = g_gate * 0.125f * L2E;
    int i0 = blockIdx.x * 32;
    for (int it = 0; it < 8; ++it) {
        int ln = g * 8 + it;
        int i = i0 + ln;
        float x0 = nf[i*3+0], x1 = nf[i*3+1], x2 = nf[i*3+2];
        float a = b1[d] + x0*w1[d] + x1*w1[64+d] + x2*w1[128+d] + t0*w1[192+d] + t1*w1[256+d];
        h1[g][d] = fmaxf(a, 0.0f);
        __syncthreads();
        float s2 = b2[d];
        #pragma unroll 8
        for (int e = 0; e < 64; ++e) s2 += h1[g][e] * w2[e*64 + d];
        hh[g][d] = s2;
        g_h[i*64 + d] = s2;
        __syncthreads();
        float q = bq[d], k = bk[d], m = bm[d];
        #pragma unroll 8
        for (int e = 0; e < 64; ++e) {
            float he = hh[g][e];
            q += he * wq[e*64 + d];
            k += he * wk[e*64 + d];
            m += he * wm[e*64 + d];
        }
        g_q[i*64 + d] = __float2bfloat16(q * qsc);
        g_k[i*64 + d] = __float2bfloat16(k);
        stg[d][ln] = m;
        if (d == 0) g_s[i] = x2;
        __syncthreads();
    }
    // transposed write-out of m
    int dd = threadIdx.x >> 2, p = threadIdx.x & 3;
    float4 v0 = *(float4*)&stg[dd][p*8];
    float4 v1 = *(float4*)&stg[dd][p*8 + 4];
    uint32_t o[4] = {pkbf(v0.x, v0.y), pkbf(v0.z, v0.w), pkbf(v1.x, v1.y), pkbf(v1.z, v1.w)};
    *(uint4*)(g_mT + (size_t)dd*NN + i0 + p*8) = *(uint4*)o;
}

// ---------------- Kernel 2: flash attention, pipelined PV, one barrier/iter -----
// 8 warps = 4x2 grid; warp tile 16x32; bf16 mma m16n8k16.
// K: 3 bufs, M: 4 bufs, P: 2 bufs (PV deferred one iteration).
#define KSTR 36
#define TILE_W (64*KSTR)          // 2304 words
#define OFF_K 0                   // 3 tiles: 0..6912
#define OFF_M (3*TILE_W)          // 6912..16128 (4 tiles)
#define OFF_Q (7*TILE_W)          // 16128
#define OFF_P (8*TILE_W)          // 18432 (2 tiles)
#define OFF_RED (10*TILE_W)       // 23040, 128 words
#define SMEM_WORDS (10*TILE_W + 128)

__global__ void __launch_bounds__(256) k_attn(const float* __restrict__ adj,
                                              const float* __restrict__ lng,
                                              const float* __restrict__ lnb) {
    extern __shared__ uint32_t smw[];
    const int t = threadIdx.x;
    const int warp = t >> 5, lane = t & 31;
    const int wr = warp >> 1, wc = warp & 1;
    const int qr = lane >> 2, four = lane & 3;
    const int r0 = blockIdx.x * 64;
    const int rowa = wr * 16 + qr;
    const uint32_t sbase = (uint32_t)__cvta_generic_to_shared(smw);

    auto cpK = [&](int tile, int buf) {
        uint32_t dk = sbase + (OFF_K + buf * TILE_W) * 4;
        #pragma unroll
        for (int rep = 0; rep < 2; ++rep) {
            int idx = t + rep * 256;
            int r = idx >> 3, c = idx & 7;
            CP16(dk + (r * KSTR + c * 4) * 4, g_k + (size_t)(tile * 64 + r) * 64 + c * 8);
        }
    };
    auto cpM = [&](int tile, int buf) {
        uint32_t dm = sbase + (OFF_M + buf * TILE_W) * 4;
        #pragma unroll
        for (int rep = 0; rep < 2; ++rep) {
            int idx = t + rep * 256;
            int r = idx >> 3, c = idx & 7;
            CP16(dm + (r * KSTR + c * 4) * 4, g_mT + (size_t)r * NN + tile * 64 + c * 8);
        }
    };
    // prologue: Q + tiles 0,1
    {
        uint32_t dq = sbase + OFF_Q * 4;
        #pragma unroll
        for (int rep = 0; rep < 2; ++rep) {
            int idx = t + rep * 256;
            int r = idx >> 3, c = idx & 7;
            CP16(dq + (r * KSTR + c * 4) * 4, g_q + (size_t)(r0 + r) * 64 + c * 8);
        }
        cpK(0, 0); cpM(0, 0); CPCOM();
        cpK(1, 1); cpM(1, 1); CPCOM();
    }

    const float sbc = g_sbc;
    const float srb0 = g_s[r0 + rowa] * sbc;       // row constants pre-multiplied
    const float srb1 = g_s[r0 + rowa + 8] * sbc;
    const float* adjr0 = adj + (size_t)(r0 + rowa) * NN + wc * 32 + 2 * four;
    const float* adjr1 = adjr0 + (size_t)8 * NN;

    const uint32_t* Qw = smw + OFF_Q;
    float* redl = (float*)(smw + OFF_RED);

    float psum0 = 0.0f, psum1 = 0.0f;
    float acc[4][4];
    #pragma unroll
    for (int ni = 0; ni < 4; ++ni)
        #pragma unroll
        for (int e = 0; e < 4; ++e) acc[ni][e] = 0.0f;

    for (int ct = 0; ct < 128; ++ct) {
        const int c0 = ct * 64;
        // adj + g_s for THIS iter (streaming: adj is read-once, keep L2 for K/M)
        float2 adjv[8], scv[4];
        #pragma unroll
        for (int ni = 0; ni < 4; ++ni) {
            scv[ni]      = *(const float2*)(g_s + c0 + wc * 32 + ni * 8 + 2 * four);
            adjv[ni*2+0] = __ldcs((const float2*)(adjr0 + c0 + ni * 8));
            adjv[ni*2+1] = __ldcs((const float2*)(adjr1 + c0 + ni * 8));
        }
        CPWAIT(1);
        __syncthreads();   // tile ct visible; P_{ct-1} stores visible; prev bufs free
        int nt = ct + 2; if (nt > 127) nt = 127;
        cpK(nt, (ct + 2) % 3); cpM(nt, (ct + 2) % 4); CPCOM();

        const uint32_t* Kb = smw + OFF_K + (ct % 3) * TILE_W;

        // S = Q K^T
        float S[4][4];
        #pragma unroll
        for (int ni = 0; ni < 4; ++ni)
            #pragma unroll
            for (int e = 0; e < 4; ++e) S[ni][e] = 0.0f;
        #pragma unroll
        for (int kk = 0; kk < 4; ++kk) {
            uint32_t a[4], b[2];
            const uint32_t* qp = Qw + rowa * KSTR + kk * 8 + four;
            a[0] = qp[0]; a[1] = qp[8 * KSTR]; a[2] = qp[4]; a[3] = qp[8 * KSTR + 4];
            #pragma unroll
            for (int ni = 0; ni < 4; ++ni) {
                const uint32_t* kp = Kb + (wc * 32 + ni * 8 + qr) * KSTR + kk * 8 + four;
                b[0] = kp[0]; b[1] = kp[4];
                mma_bf16(S[ni], a, b);
            }
        }

        // deferred PV_{ct-1}: covers adj-load latency, overlaps HMMA with MUFU below
        if (ct > 0) {
            const uint32_t* Pp = smw + OFF_P + ((ct - 1) & 1) * TILE_W;
            const uint32_t* Mb = smw + OFF_M + ((ct - 1) % 4) * TILE_W;
            #pragma unroll
            for (int kk = 0; kk < 4; ++kk) {
                uint32_t a[4], b[2];
                const uint32_t* pp = Pp + rowa * KSTR + kk * 8 + four;
                a[0] = pp[0]; a[1] = pp[8 * KSTR]; a[2] = pp[4]; a[3] = pp[8 * KSTR + 4];
                #pragma unroll
                for (int ni = 0; ni < 4; ++ni) {
                    const uint32_t* mp = Mb + (wc * 32 + ni * 8 + qr) * KSTR + kk * 8 + four;
                    b[0] = mp[0]; b[1] = mp[4];
                    mma_bf16(acc[ni], a, b);
                }
            }
        }

        // p = adj ? exp2(s + sr*sc*sbc) : 0  -> P buf ct%2
        uint32_t* Pw = smw + OFF_P + (ct & 1) * TILE_W;
        #pragma unroll
        for (int ni = 0; ni < 4; ++ni) {
            float2 a0 = adjv[ni*2+0], a1 = adjv[ni*2+1], sc2 = scv[ni];
            float p00 = (a0.x == 0.0f) ? 0.0f : ex2f(fmaf(srb0, sc2.x, S[ni][0]));
            float p01 = (a0.y == 0.0f) ? 0.0f : ex2f(fmaf(srb0, sc2.y, S[ni][1]));
            float p10 = (a1.x == 0.0f) ? 0.0f : ex2f(fmaf(srb1, sc2.x, S[ni][2]));
            float p11 = (a1.y == 0.0f) ? 0.0f : ex2f(fmaf(srb1, sc2.y, S[ni][3]));
            psum0 += p00 + p01;
            psum1 += p10 + p11;
            int cw = wc * 16 + ni * 4 + four;
            Pw[rowa * KSTR + cw]       = pkbf(p00, p01);
            Pw[(rowa + 8) * KSTR + cw] = pkbf(p10, p11);
        }
    }
    CPWAIT(0);
    __syncthreads();   // P_127 visible; no cp.async in flight

    // trailing PV_127
    {
        const uint32_t* Pp = smw + OFF_P + (127 & 1) * TILE_W;
        const uint32_t* Mb = smw + OFF_M + (127 % 4) * TILE_W;
        #pragma unroll
        for (int kk = 0; kk < 4; ++kk) {
            uint32_t a[4], b[2];
            const uint32_t* pp = Pp + rowa * KSTR + kk * 8 + four;
            a[0] = pp[0]; a[1] = pp[8 * KSTR]; a[2] = pp[4]; a[3] = pp[8 * KSTR + 4];
            #pragma unroll
            for (int ni = 0; ni < 4; ++ni) {
                const uint32_t* mp = Mb + (wc * 32 + ni * 8 + qr) * KSTR + kk * 8 + four;
                b[0] = mp[0]; b[1] = mp[4];
                mma_bf16(acc[ni], a, b);
            }
        }
    }

    // l reduction
    psum0 += __shfl_xor_sync(0xffffffffu, psum0, 1);
    psum0 += __shfl_xor_sync(0xffffffffu, psum0, 2);
    psum1 += __shfl_xor_sync(0xffffffffu, psum1, 1);
    psum1 += __shfl_xor_sync(0xffffffffu, psum1, 2);
    if (four == 0) {
        redl[wc * 64 + rowa]     = psum0;
        redl[wc * 64 + rowa + 8] = psum1;
    }
    __syncthreads();
    float inv0 = 1.0f / (redl[rowa]     + redl[64 + rowa]);
    float inv1 = 1.0f / (redl[rowa + 8] + redl[64 + rowa + 8]);

    // z = h + O/l -> zbuf (reuses K region, disjoint from P/M bufs), layernorm
    float* zbuf = (float*)smw;   // 64 x stride 66 = 4224 words < OFF_M
    #pragma unroll
    for (int ni = 0; ni < 4; ++ni) {
        int col = wc * 32 + ni * 8 + 2 * four;
        float2 h0 = *(const float2*)(g_h + (size_t)(r0 + rowa) * 64 + col);
        float2 h1 = *(const float2*)(g_h + (size_t)(r0 + rowa + 8) * 64 + col);
        float2 z0, z1;
        z0.x = h0.x + acc[ni][0] * inv0;  z0.y = h0.y + acc[ni][1] * inv0;
        z1.x = h1.x + acc[ni][2] * inv1;  z1.y = h1.y + acc[ni][3] * inv1;
        *(float2*)(zbuf + rowa * 66 + col)       = z0;
        *(float2*)(zbuf + (rowa + 8) * 66 + col) = z1;
    }
    __syncthreads();
    if (t < 64) {
        float sum = 0.0f;
        #pragma unroll 16
        for (int c = 0; c < 64; ++c) sum += zbuf[t * 66 + c];
        float mu = sum * (1.0f / 64.0f);
        float sq = 0.0f;
        #pragma unroll 16
        for (int c = 0; c < 64; ++c) { float dz = zbuf[t * 66 + c] - mu; sq += dz * dz; }
        float rstd = rsqrtf(sq * (1.0f / 64.0f) + 1e-5f);
        #pragma unroll 16
        for (int c = 0; c < 64; ++c)
            g_emb[(size_t)(r0 + t) * 64 + c] = (zbuf[t * 66 + c] - mu) * rstd * lng[c] + lnb[c];
    }
}

// ---------------- Kernel 3: DQN head — warp per node, split accumulators --------
__global__ void __launch_bounds__(256) k_head(
    const float* __restrict__ sa, const float* __restrict__ wa1,
    const float* __restrict__ ba1, const float* __restrict__ wa2,
    const float* __restrict__ ba2, float* __restrict__ out) {
    __shared__ float swa1[66*64];
    __shared__ float swa2[64*3];
    int t = threadIdx.x;
    for (int idx = t; idx < 66*64; idx += 256) swa1[idx] = wa1[idx];
    if (t < 192) swa2[t] = wa2[t];
    __syncthreads();
    int warp = t >> 5, lane = t & 31;
    float b0 = ba1[2*lane], b1 = ba1[2*lane+1];
    for (int it = 0; it < 4; ++it) {
        int i = blockIdx.x * 32 + it * 8 + warp;
        float2 e = *(const float2*)(g_emb + (size_t)i * 64 + 2 * lane);
        float2 s2 = *(const float2*)(sa + i * 2);
        float acc0a = b0, acc1a = b1, acc0b = 0.0f, acc1b = 0.0f;
        #pragma unroll
        for (int ee = 0; ee < 32; ++ee) {
            float va = __shfl_sync(0xffffffffu, (ee & 1) ? e.y : e.x, ee >> 1);
            float vb = __shfl_sync(0xffffffffu, (ee & 1) ? e.y : e.x, (ee + 32) >> 1);
            float2 wa = *(const float2*)(swa1 + ee * 64 + 2 * lane);
            float2 wb = *(const float2*)(swa1 + (ee + 32) * 64 + 2 * lane);
            acc0a += va * wa.x; acc1a += va * wa.y;
            acc0b += vb * wb.x; acc1b += vb * wb.y;
        }
        { float2 w = *(const float2*)(swa1 + 64*64 + 2*lane); acc0a += s2.x * w.x; acc1a += s2.x * w.y; }
        { float2 w = *(const float2*)(swa1 + 65*64 + 2*lane); acc0b += s2.y * w.x; acc1b += s2.y * w.y; }
        float acc0 = fmaxf(acc0a + acc0b, 0.0f);
        float acc1 = fmaxf(acc1a + acc1b, 0.0f);
        float o0 = acc0 * swa2[(2*lane)*3+0] + acc1 * swa2[(2*lane+1)*3+0];
        float o1 = acc0 * swa2[(2*lane)*3+1] + acc1 * swa2[(2*lane+1)*3+1];
        float o2 = acc0 * swa2[(2*lane)*3+2] + acc1 * swa2[(2*lane+1)*3+2];
        #pragma unroll
        for (int off = 16; off > 0; off >>= 1) {
            o0 += __shfl_xor_sync(0xffffffffu, o0, off);
            o1 += __shfl_xor_sync(0xffffffffu, o1, off);
            o2 += __shfl_xor_sync(0xffffffffu, o2, off);
        }
        if (lane == 0) {
            out[i*3+0] = o0 + ba2[0];
            out[i*3+1] = o1 + ba2[1];
            out[i*3+2] = o2 + ba2[2];
        }
    }
}

extern "C" void kernel_launch(void* const* d_in, const int* in_sizes, int n_in,
                              void* d_out, int out_size) {
    const float* nf    = (const float*)d_in[0];
    const float* adj   = (const float*)d_in[1];
    const float* trig  = (const float*)d_in[2];
    const float* sa    = (const float*)d_in[3];
    const float* w1    = (const float*)d_in[4];
    const float* b1    = (const float*)d_in[5];
    const float* w2    = (const float*)d_in[6];
    const float* b2    = (const float*)d_in[7];
    const float* wq    = (const float*)d_in[8];
    const float* bq    = (const float*)d_in[9];
    const float* wk    = (const float*)d_in[10];
    const float* bk    = (const float*)d_in[11];
    const float* wg    = (const float*)d_in[12];
    const float* bg    = (const float*)d_in[13];
    const float* sbias = (const float*)d_in[14];
    const float* wm    = (const float*)d_in[15];
    const float* bm    = (const float*)d_in[16];
    const float* lng   = (const float*)d_in[17];
    const float* lnb   = (const float*)d_in[18];
    const float* wa1   = (const float*)d_in[19];
    const float* ba1   = (const float*)d_in[20];
    const float* wa2   = (const float*)d_in[21];
    const float* ba2   = (const float*)d_in[22];
    float* out = (float*)d_out;

    const int smem = SMEM_WORDS * 4;  // 92,672 B
    cudaFuncSetAttribute(k_attn, cudaFuncAttributeMaxDynamicSharedMemorySize, smem);

    k_scalars<<<1, 64>>>(trig, wg, bg, sbias);
    k_mlp<<<256, 256>>>(nf, trig, w1, b1, w2, b2, wq, bq, wk, bk, wm, bm);
    k_attn<<<128, 256, smem>>>(adj, lng, lnb);
    k_head<<<256, 256>>>(sa, wa1, ba1, wa2, ba2, out);
}